// round 13
// baseline (speedup 1.0000x reference)
#include <cuda_runtime.h>
#include <math.h>

// z[b] = sum_t x[b,t]*K[t] + z0 + e
// K[t] = sum_h w_h*b_h*a_h^(T-1-t),  z0 = sum_h w_h*c_h*(1-a_h^T)/(1-a_h)
// Block j computes K for exponents s in [16j,16j+16) entirely in smem and
// RED-adds its dot contribution (all 64 rows) into out. No K in gmem,
// no fences, no inter-block handshake. out zeroed by a memset graph node.
#define TLEN 4096
#define HDIM 512
#define BATCH 64
#define CHUNK 16
#define NCHUNK (TLEN / CHUNK)   // 256 blocks

__global__ __launch_bounds__(HDIM) void fused_kernel(
    const float* __restrict__ x, const float* __restrict__ a,
    const float* __restrict__ b, const float* __restrict__ c,
    const float* __restrict__ w, const float* __restrict__ e,
    float* __restrict__ out)
{
    __shared__ float part[CHUNK][HDIM];   // 32 KB
    __shared__ float kc[CHUNK];
    __shared__ float zp[16];
    __shared__ float s_z0;

    const int tid = threadIdx.x;
    const int j   = blockIdx.x;           // exponents s in [16j, 16j+16)
    const int warp = tid >> 5, lane = tid & 31;
    const int row  = tid >> 3, sub = tid & 7;   // dot layout: 8 thr/row

    // ---- prefetch this block's x window (hides under seed+chain) ----
    // s = 16j+i <-> t = 4095-s; block covers t in [t0, t0+16)
    const int t0 = TLEN - CHUNK * (j + 1);
    const float2 xv = *(const float2*)(x + (size_t)row * TLEN + t0 + 2 * sub);

    // ---- phase 1: K chunk (identical math to proven build_K) ----
    const float af = a[tid];
    const float bf = b[tid];
    const float wf = w[tid];
    const float l2a = log2f(af);          // relative-accurate (NOT __log2f)
    float p = (wf * bf) * exp2f((float)(j * CHUNK) * l2a);

    if (j == 0) {                          // z0 partials
        const float aT  = exp2f((float)TLEN * l2a);
        const float geo = (1.0f - aT) / (1.0f - af);
        float term = wf * c[tid] * geo;
        #pragma unroll
        for (int off = 16; off; off >>= 1)
            term += __shfl_down_sync(0xffffffffu, term, off);
        if (lane == 0) zp[warp] = term;
    }

    #pragma unroll
    for (int i = 0; i < CHUNK; i++) { part[i][tid] = p; p *= af; }
    __syncthreads();

    // warp i reduces the h-dimension for t-offset i -> kc[i] (smem only)
    float s = 0.0f;
    #pragma unroll
    for (int k = 0; k < HDIM / 32; k++) s += part[warp][lane + 32 * k];
    #pragma unroll
    for (int off = 16; off; off >>= 1) s += __shfl_down_sync(0xffffffffu, s, off);
    if (lane == 0) kc[warp] = s;

    if (j == 0 && tid == 0) {
        float sz = 0.0f;
        #pragma unroll
        for (int i = 0; i < 16; i++) sz += zp[i];
        s_z0 = sz + e[0];
    }
    __syncthreads();

    // ---- phase 2: dot contribution, all 64 rows, RED into out ----
    // x element t0+u pairs with kc[15-u]; this thread covers u = 2sub, 2sub+1
    float d = xv.x * kc[15 - 2 * sub] + xv.y * kc[14 - 2 * sub];
    d += __shfl_down_sync(0xffffffffu, d, 4, 8);
    d += __shfl_down_sync(0xffffffffu, d, 2, 8);
    d += __shfl_down_sync(0xffffffffu, d, 1, 8);
    if (sub == 0) atomicAdd(&out[row], d);       // REDG, fire-and-forget

    // block 0 contributes z0 + e to every row
    if (j == 0 && tid < BATCH) atomicAdd(&out[tid], s_z0);
}

extern "C" void kernel_launch(void* const* d_in, const int* in_sizes, int n_in,
                              void* d_out, int out_size)
{
    const float* x = (const float*)d_in[0];   // [B, T]
    const float* a = (const float*)d_in[1];   // [H]
    const float* b = (const float*)d_in[2];   // [H]
    const float* c = (const float*)d_in[3];   // [H]
    const float* w = (const float*)d_in[4];   // [H]
    const float* e = (const float*)d_in[5];   // [1]
    float* out = (float*)d_out;               // [B]

    // zero the accumulator (graph-capturable memset node, stream-ordered)
    cudaMemsetAsync(d_out, 0, BATCH * sizeof(float), 0);
    fused_kernel<<<NCHUNK, HDIM>>>(x, a, b, c, w, e, out);
}

// round 14
// speedup vs baseline: 1.2031x; 1.2031x over previous
#include <cuda_runtime.h>
#include <math.h>

// z[b] = sum_t x[b,t]*K[t] + z0 + e
// K[t] = sum_h w_h*b_h*a_h^(T-1-t),  z0 = sum_h w_h*c_h*(1-a_h^T)/(1-a_h)
#define TLEN 4096
#define HDIM 512
#define BATCH 64
#define CHUNK 16
#define NCHUNK (TLEN / CHUNK)   // 256 blocks

// Scratch (__device__ globals; no allocations allowed)
__device__ __align__(16) float g_K[TLEN];
__device__ float g_z0;

// Kernel 1: K chunk of 16 t's per block, seed via accurate log2f/exp2f.
// Also prefetches the x matrix into L2 (1 line per 16 threads) so the
// dependent dot kernel's loads are L2 hits instead of DRAM misses.
__global__ __launch_bounds__(HDIM) void build_K_kernel(
    const float* __restrict__ x,
    const float* __restrict__ a, const float* __restrict__ b,
    const float* __restrict__ c, const float* __restrict__ w)
{
    __shared__ float part[CHUNK][HDIM];   // 32 KB
    __shared__ float zp[16];
    const int h = threadIdx.x;
    const int j = blockIdx.x;             // exponents s in [16j, 16j+16)
    const int warp = h >> 5, lane = h & 31;

    // ---- fire-and-forget L2 warm of x: 8192 lines over 131072 threads ----
    if ((h & 15) == 0) {
        const size_t line = ((size_t)j * HDIM + h) >> 4;   // 0..8191
        asm volatile("prefetch.global.L2 [%0];" :: "l"(x + line * 32));
    }

    // issue all LDGs up front so they overlap the MUFU chain
    const float af = a[h];
    const float bf = b[h];
    const float wf = w[h];

    const float l2a = log2f(af);          // relative-accurate (NOT __log2f)
    float p = (wf * bf) * exp2f((float)(j * CHUNK) * l2a);

    #pragma unroll
    for (int i = 0; i < CHUNK; i++) { part[i][h] = p; p *= af; }

    if (j == 0) {                          // z0 = sum_h w*c*(1-a^T)/(1-a)
        const float aT  = exp2f((float)TLEN * l2a);
        const float geo = (1.0f - aT) / (1.0f - af);
        float term = wf * c[h] * geo;
        #pragma unroll
        for (int off = 16; off; off >>= 1)
            term += __shfl_down_sync(0xffffffffu, term, off);
        if (lane == 0) zp[warp] = term;
    }
    __syncthreads();

    // warp i reduces the h-dimension for t-offset i
    float s = 0.0f;
    #pragma unroll
    for (int k = 0; k < HDIM / 32; k++) s += part[warp][lane + 32 * k];
    #pragma unroll
    for (int off = 16; off; off >>= 1) s += __shfl_down_sync(0xffffffffu, s, off);
    if (lane == 0) g_K[TLEN - 1 - (j * CHUNK + warp)] = s;

    if (j == 0 && h == 0) {
        float sz = 0.0f;
        #pragma unroll
        for (int i = 0; i < 16; i++) sz += zp[i];
        g_z0 = sz;
    }

    // all K/z0 stores issued -> release the dependent grid
    asm volatile("griddepcontrol.launch_dependents;");
}

// Kernel 2 (PDL secondary): one block per batch row, 1024 threads,
// one float4 of x (L2-warm) and K per thread.
__global__ __launch_bounds__(1024) void dot_kernel(
    const float* __restrict__ x, const float* __restrict__ e,
    float* __restrict__ out)
{
    const int row = blockIdx.x;
    const int tid = threadIdx.x;

    // independent prologue (overlaps primary grid tail)
    const float4 xv = ((const float4*)(x + (size_t)row * TLEN))[tid];
    const float ev = e[0];

    asm volatile("griddepcontrol.wait;" ::: "memory");

    const float4 kv = __ldcg(&((const float4*)g_K)[tid]);
    const float z0 = __ldcg(&g_z0);

    float s = xv.x * kv.x + xv.y * kv.y + xv.z * kv.z + xv.w * kv.w;
    // fold z0+e into warp 0 lane 0's partial so the tail has no extra add
    if (tid == 0) s += z0 + ev;
    #pragma unroll
    for (int off = 16; off; off >>= 1) s += __shfl_down_sync(0xffffffffu, s, off);

    __shared__ float sp[32];
    const int warp = tid >> 5, lane = tid & 31;
    if (lane == 0) sp[warp] = s;
    __syncthreads();

    if (warp == 0) {
        float t = sp[lane];
        #pragma unroll
        for (int off = 16; off; off >>= 1) t += __shfl_down_sync(0xffffffffu, t, off);
        if (lane == 0) out[row] = t;
    }
}

extern "C" void kernel_launch(void* const* d_in, const int* in_sizes, int n_in,
                              void* d_out, int out_size)
{
    const float* x = (const float*)d_in[0];   // [B, T]
    const float* a = (const float*)d_in[1];   // [H]
    const float* b = (const float*)d_in[2];   // [H]
    const float* c = (const float*)d_in[3];   // [H]
    const float* w = (const float*)d_in[4];   // [H]
    const float* e = (const float*)d_in[5];   // [1]
    float* out = (float*)d_out;               // [B]

    build_K_kernel<<<NCHUNK, HDIM>>>(x, a, b, c, w);

    // dot as programmatic dependent of build_K (PDL edge; graph-capturable)
    cudaLaunchAttribute attrs[1];
    attrs[0].id = cudaLaunchAttributeProgrammaticStreamSerialization;
    attrs[0].val.programmaticStreamSerializationAllowed = 1;
    cudaLaunchConfig_t cfg = {};
    cfg.gridDim  = dim3(BATCH);
    cfg.blockDim = dim3(1024);
    cfg.dynamicSmemBytes = 0;
    cfg.stream = 0;
    cfg.attrs = attrs;
    cfg.numAttrs = 1;
    cudaLaunchKernelEx(&cfg, dot_kernel, x, e, out);
}